// round 9
// baseline (speedup 1.0000x reference)
#include <cuda_runtime.h>

#define BB 32
#define TT 512
#define UU 512
#define NG 1536          // 3*U
#define OC 1024          // 2*U output channels
#define NBLK 64          // scan blocks (each owns 8 cols of BOTH dirs)

// x-gates scratch: [dir][B*T][3U] fp32 (192 MB, static device allocation)
__device__ float    g_xg[(size_t)2 * BB * TT * NG];
// per-step rh = r * h_prev exchange buffer [dir][b][u]
__device__ float    g_rh[2 * BB * UU];
// split arrive/wait barriers: per-step counters (reset at kernel end)
__device__ int      g_bar1[2 * TT];
__device__ int      g_bar2[2 * TT];
__device__ int      g_done;

__device__ __forceinline__ float hsig(float v) {
    return fminf(fmaxf(0.2f * v + 0.5f, 0.0f), 1.0f);
}

// packed dual-FMA: acc.{lo,hi} += a.{lo,hi} * b.{lo,hi}
#define FMA2(acc, a, b) \
    asm("fma.rn.f32x2 %0, %1, %2, %0;" : "+l"(acc) : "l"(a), "l"(b))

__device__ __forceinline__ float pair_sum(unsigned long long v) {
    return __uint_as_float((unsigned)v) + __uint_as_float((unsigned)(v >> 32));
}

// ---------------------------------------------------------------------------
// Phase 1: Xg[dir][m][n] = x[m][:] @ W_dir[:][n] + bias_dir[n]
// M=16384, K=512, N=1536. BM=BN=128, BK=16, 256 thr, 8x8 reg tile,
// register-prefetch double buffering. (unchanged from r7/r8)
// ---------------------------------------------------------------------------
#define XS 132           // padded smem row stride (floats)

__global__ void __launch_bounds__(256, 2)
xgemm_kernel(const float* __restrict__ A,
             const float* __restrict__ Wf, const float* __restrict__ bf,
             const float* __restrict__ Wb, const float* __restrict__ bb)
{
    const int dir = blockIdx.z;
    const float* __restrict__ W    = dir ? Wb : Wf;
    const float* __restrict__ bias = dir ? bb : bf;
    const int m0 = blockIdx.y * 128;
    const int n0 = blockIdx.x * 128;

    __shared__ float As[16 * XS];   // [k][m]
    __shared__ float Bs[16 * XS];   // [k][n]

    const int tid = threadIdx.x;
    const int tx = tid & 15;        // n group (8 cols)
    const int ty = tid >> 4;        // m group (8 rows)

    const int arow = tid >> 1;             // 0..127
    const int akq  = (tid & 1) << 3;       // 0 or 8
    const int bk = tid >> 4;               // 0..15
    const int bn = (tid & 15) << 3;        // 0..120

    const float* Aptr = A + (size_t)(m0 + arow) * 512 + akq;
    const float* Wptr = W + (size_t)bk * NG + n0 + bn;

    float acc[8][8];
#pragma unroll
    for (int i = 0; i < 8; ++i)
#pragma unroll
        for (int j = 0; j < 8; ++j) acc[i][j] = 0.0f;

    float4 a0 = *(const float4*)(Aptr + 0);
    float4 a1 = *(const float4*)(Aptr + 4);
    float4 b0 = *(const float4*)(Wptr + 0);
    float4 b1 = *(const float4*)(Wptr + 4);

    {
        float av[8] = {a0.x,a0.y,a0.z,a0.w,a1.x,a1.y,a1.z,a1.w};
#pragma unroll
        for (int j = 0; j < 8; ++j) As[(akq + j) * XS + arow] = av[j];
        *(float4*)&Bs[bk * XS + bn]     = b0;
        *(float4*)&Bs[bk * XS + bn + 4] = b1;
    }
    __syncthreads();

    for (int kt = 0; kt < 32; ++kt) {
        const int k_next = (kt + 1) << 4;
        if (kt < 31) {
            a0 = *(const float4*)(Aptr + k_next + 0);
            a1 = *(const float4*)(Aptr + k_next + 4);
            b0 = *(const float4*)(Wptr + (size_t)k_next * NG + 0);
            b1 = *(const float4*)(Wptr + (size_t)k_next * NG + 4);
        }

#pragma unroll
        for (int kk = 0; kk < 16; ++kk) {
            float4 av0 = *(const float4*)&As[kk * XS + ty * 8];
            float4 av1 = *(const float4*)&As[kk * XS + ty * 8 + 4];
            float4 bv0 = *(const float4*)&Bs[kk * XS + tx * 8];
            float4 bv1 = *(const float4*)&Bs[kk * XS + tx * 8 + 4];
            float aa[8]  = {av0.x,av0.y,av0.z,av0.w,av1.x,av1.y,av1.z,av1.w};
            float bb2[8] = {bv0.x,bv0.y,bv0.z,bv0.w,bv1.x,bv1.y,bv1.z,bv1.w};
#pragma unroll
            for (int i = 0; i < 8; ++i)
#pragma unroll
                for (int j = 0; j < 8; ++j)
                    acc[i][j] = fmaf(aa[i], bb2[j], acc[i][j]);
        }

        if (kt < 31) {
            __syncthreads();
            float av[8] = {a0.x,a0.y,a0.z,a0.w,a1.x,a1.y,a1.z,a1.w};
#pragma unroll
            for (int j = 0; j < 8; ++j) As[(akq + j) * XS + arow] = av[j];
            *(float4*)&Bs[bk * XS + bn]     = b0;
            *(float4*)&Bs[bk * XS + bn + 4] = b1;
            __syncthreads();
        }
    }

    float* __restrict__ Cd = g_xg + (size_t)dir * BB * TT * NG;
    const int nbase = n0 + tx * 8;
    float4 bi0 = *(const float4*)(bias + nbase);
    float4 bi1 = *(const float4*)(bias + nbase + 4);
#pragma unroll
    for (int i = 0; i < 8; ++i) {
        const int m = m0 + ty * 8 + i;
        float4 o0, o1;
        o0.x = acc[i][0] + bi0.x; o0.y = acc[i][1] + bi0.y;
        o0.z = acc[i][2] + bi0.z; o0.w = acc[i][3] + bi0.w;
        o1.x = acc[i][4] + bi1.x; o1.y = acc[i][5] + bi1.y;
        o1.z = acc[i][6] + bi1.z; o1.w = acc[i][7] + bi1.w;
        *(float4*)&Cd[(size_t)m * NG + nbase]     = o0;
        *(float4*)&Cd[(size_t)m * NG + nbase + 4] = o1;
    }
}

// ---------------------------------------------------------------------------
// Split arrive/wait software barrier over per-step counters.
// arrive: fence + block-sync + one atomicAdd.  wait: tid0 poll + block-sync.
// ---------------------------------------------------------------------------
__device__ __forceinline__ void bar_arrive(int* cnt, int tid)
{
    __threadfence();                 // release this thread's global writes
    __syncthreads();                 // all threads' writes fenced
    if (tid == 0) atomicAdd(cnt, 1);
}

__device__ __forceinline__ void bar_wait(int* cnt, int tid)
{
    if (tid == 0) {
        while (*(volatile int*)cnt < NBLK) { }
        __threadfence();             // acquire
    }
    __syncthreads();
}

// ---------------------------------------------------------------------------
// Phase 2: persistent scan, BOTH directions per block.
// 64 blocks x 256 threads. Block owns 8 cols of fwd AND bwd GRU.
// Thread = (batch b, column c); full K=512 in-register, packed f32x2 FMA.
// Barrier latency of one direction hides under the other direction's GEMM.
// smem floats: weights 2 * 3*8*516 = 24768 | sHf,sHb 2 * 32*516 = 33024
// total 57792 floats = 231,168 B  (1 block/SM)
// ---------------------------------------------------------------------------
#define SWS 516          // weight row stride (floats)
#define HHS 516          // h row stride (floats)
#define WD  (3 * 8 * SWS)
#define SCAN_SMEM_BYTES ((2 * WD + 2 * BB * HHS) * 4)

// stage 16 float4 per thread: strided source (h history in out)
#define LOAD_H(dst, hsrc)                                                     \
    {                                                                         \
        float4 t0[8], t1[8];                                                  \
        _Pragma("unroll")                                                     \
        for (int r = 0; r < 8; ++r) {                                         \
            const int i = tid + (r << 8);                                     \
            t0[r] = __ldcg((const float4*)((hsrc) +                           \
                     (size_t)(i >> 7) * TT * OC + ((i & 127) << 2)));         \
        }                                                                     \
        _Pragma("unroll")                                                     \
        for (int r = 0; r < 8; ++r) {                                         \
            const int i = tid + ((r + 8) << 8);                               \
            t1[r] = __ldcg((const float4*)((hsrc) +                           \
                     (size_t)(i >> 7) * TT * OC + ((i & 127) << 2)));         \
        }                                                                     \
        _Pragma("unroll")                                                     \
        for (int r = 0; r < 8; ++r) {                                         \
            const int i = tid + (r << 8);                                     \
            *(float4*)&(dst)[(i >> 7) * HHS + ((i & 127) << 2)] = t0[r];      \
        }                                                                     \
        _Pragma("unroll")                                                     \
        for (int r = 0; r < 8; ++r) {                                         \
            const int i = tid + ((r + 8) << 8);                               \
            *(float4*)&(dst)[(i >> 7) * HHS + ((i & 127) << 2)] = t1[r];      \
        }                                                                     \
    }

// stage 16 float4 per thread: contiguous source (g_rh)
#define LOAD_RH(dst, rsrc)                                                    \
    {                                                                         \
        float4 t0[8], t1[8];                                                  \
        _Pragma("unroll")                                                     \
        for (int r = 0; r < 8; ++r)                                           \
            t0[r] = __ldcg((const float4*)((rsrc) + ((tid + (r << 8)) << 2)));\
        _Pragma("unroll")                                                     \
        for (int r = 0; r < 8; ++r)                                           \
            t1[r] = __ldcg((const float4*)((rsrc) +                           \
                                           ((tid + ((r + 8) << 8)) << 2)));   \
        _Pragma("unroll")                                                     \
        for (int r = 0; r < 8; ++r) {                                         \
            const int i = tid + (r << 8);                                     \
            *(float4*)&(dst)[(i >> 7) * HHS + ((i & 127) << 2)] = t0[r];      \
        }                                                                     \
        _Pragma("unroll")                                                     \
        for (int r = 0; r < 8; ++r) {                                         \
            const int i = tid + ((r + 8) << 8);                               \
            *(float4*)&(dst)[(i >> 7) * HHS + ((i & 127) << 2)] = t1[r];      \
        }                                                                     \
    }

__global__ void __launch_bounds__(256, 1)
scan_kernel(const float* __restrict__ Uf,
            const float* __restrict__ Ub,
            float* __restrict__ out)
{
    extern __shared__ float sm[];
    float* sWf = sm;                     // fwd weights: z @0, r @4128, h @8256
    float* sWb = sm + WD;                // bwd weights
    float* sHf = sm + 2 * WD;            // fwd h staging [b][u] stride 516
    float* sHb = sHf + BB * HHS;         // bwd h staging

    const int tid   = threadIdx.x;
    const int cg    = blockIdx.x;        // 0..63
    const int hbase = cg << 3;

    // --- weight slices, loaded ONCE, transposed to [c][u] ---
    for (int i = tid; i < 4096; i += 256) {
        const int u  = i >> 3;
        const int cc = i & 7;
        const size_t srcf = (size_t)u * NG + hbase + cc;
        sWf[cc * SWS + u]            = Uf[srcf];
        sWf[4128 + cc * SWS + u]     = Uf[srcf + UU];
        sWf[8256 + cc * SWS + u]     = Uf[srcf + 2 * UU];
        sWb[cc * SWS + u]            = Ub[srcf];
        sWb[4128 + cc * SWS + u]     = Ub[srcf + UU];
        sWb[8256 + cc * SWS + u]     = Ub[srcf + 2 * UU];
    }

    const int b = tid >> 3;              // 0..31
    const int c = tid & 7;               // 0..7
    const int j = hbase + c;

    const ulonglong2* __restrict__ wzf = (const ulonglong2*)(sWf + c * SWS);
    const ulonglong2* __restrict__ wrf = (const ulonglong2*)(sWf + 4128 + c * SWS);
    const ulonglong2* __restrict__ whf = (const ulonglong2*)(sWf + 8256 + c * SWS);
    const ulonglong2* __restrict__ wzb = (const ulonglong2*)(sWb + c * SWS);
    const ulonglong2* __restrict__ wrb = (const ulonglong2*)(sWb + 4128 + c * SWS);
    const ulonglong2* __restrict__ whb = (const ulonglong2*)(sWb + 8256 + c * SWS);
    const ulonglong2* __restrict__ hvf = (const ulonglong2*)(sHf + b * HHS);
    const ulonglong2* __restrict__ hvb = (const ulonglong2*)(sHb + b * HHS);

    const size_t xg_f = ((size_t)0 * BB * TT + (size_t)b * TT) * NG;
    const size_t xg_b = ((size_t)1 * BB * TT + (size_t)b * TT) * NG;
    const size_t out_b_row = (size_t)b * TT;

    __syncthreads();                     // weights ready

    for (int s = 0; s < TT; ++s) {
        // ---- x-gate + own h_prev prefetch (both dirs) ----
        const float* __restrict__ xrf = g_xg + xg_f + (size_t)s * NG;
        const float* __restrict__ xrb = g_xg + xg_b + (size_t)(TT - 1 - s) * NG;
        const float xzf = __ldg(xrf + j);
        const float xrf_ = __ldg(xrf + UU + j);
        const float xhf = __ldg(xrf + 2 * UU + j);
        const float xzb = __ldg(xrb + j);
        const float xrb_ = __ldg(xrb + UU + j);
        const float xhb = __ldg(xrb + 2 * UU + j);
        float hpf = 0.0f, hpb = 0.0f;
        if (s > 0) {
            hpf = __ldcg(out + (out_b_row + (s - 1)) * OC + j);
            hpb = __ldcg(out + (out_b_row + (s - 1)) * OC + UU + j);
        }

        // ---- stage h_f ----
        if (s == 0) {
            for (int i = tid; i < BB * HHS; i += 256) sHf[i] = 0.0f;
        } else {
            const float* hsrc = out + (size_t)(s - 1) * OC;     // dir 0
            LOAD_H(sHf, hsrc);
        }
        __syncthreads();

        // ---- A_f: fwd z/r gates ----
        unsigned long long az0 = 0ull, az1 = 0ull, ar0 = 0ull, ar1 = 0ull;
#pragma unroll 8
        for (int uu = 0; uu < 128; ++uu) {
            ulonglong2 hv = hvf[uu];
            ulonglong2 w1 = wzf[uu];
            ulonglong2 w2 = wrf[uu];
            FMA2(az0, hv.x, w1.x); FMA2(az1, hv.y, w1.y);
            FMA2(ar0, hv.x, w2.x); FMA2(ar1, hv.y, w2.y);
        }
        float rzf, rzhf;
        {
            const float z = hsig(xzf + pair_sum(az0) + pair_sum(az1));
            const float r = hsig(xrf_ + pair_sum(ar0) + pair_sum(ar1));
            rzf  = z;
            rzhf = z * hpf;
            __stcg(&g_rh[(b << 9) + j], r * hpf);
        }
        bar_arrive(&g_bar1[s], tid);

        // ---- stage h_b ----
        if (s == 0) {
            for (int i = tid; i < BB * HHS; i += 256) sHb[i] = 0.0f;
        } else {
            const float* hsrc = out + (size_t)(s - 1) * OC + UU; // dir 1
            LOAD_H(sHb, hsrc);
        }
        __syncthreads();

        // ---- A_b: bwd z/r gates ----
        az0 = 0ull; az1 = 0ull; ar0 = 0ull; ar1 = 0ull;
#pragma unroll 8
        for (int uu = 0; uu < 128; ++uu) {
            ulonglong2 hv = hvb[uu];
            ulonglong2 w1 = wzb[uu];
            ulonglong2 w2 = wrb[uu];
            FMA2(az0, hv.x, w1.x); FMA2(az1, hv.y, w1.y);
            FMA2(ar0, hv.x, w2.x); FMA2(ar1, hv.y, w2.y);
        }
        float rzb, rzhb;
        {
            const float z = hsig(xzb + pair_sum(az0) + pair_sum(az1));
            const float r = hsig(xrb_ + pair_sum(ar0) + pair_sum(ar1));
            rzb  = z;
            rzhb = z * hpb;
            __stcg(&g_rh[(1 << 14) + (b << 9) + j], r * hpb);
        }
        bar_arrive(&g_bar1[TT + s], tid);

        // ---- B_f: fwd candidate (waits should be nearly free) ----
        bar_wait(&g_bar1[s], tid);
        LOAD_RH(sHf, g_rh);
        __syncthreads();
        unsigned long long ah0 = 0ull, ah1 = 0ull;
#pragma unroll 8
        for (int uu = 0; uu < 128; ++uu) {
            ulonglong2 hv = hvf[uu];
            ulonglong2 w1 = whf[uu];
            FMA2(ah0, hv.x, w1.x); FMA2(ah1, hv.y, w1.y);
        }
        {
            const float cand = tanhf(xhf + pair_sum(ah0) + pair_sum(ah1));
            const float hnew = rzhf + (1.0f - rzf) * cand;
            __stcg(&out[(out_b_row + s) * OC + j], hnew);
        }
        bar_arrive(&g_bar2[s], tid);

        // ---- B_b: bwd candidate ----
        bar_wait(&g_bar1[TT + s], tid);
        LOAD_RH(sHb, g_rh + (1 << 14));
        __syncthreads();
        ah0 = 0ull; ah1 = 0ull;
#pragma unroll 8
        for (int uu = 0; uu < 128; ++uu) {
            ulonglong2 hv = hvb[uu];
            ulonglong2 w1 = whb[uu];
            FMA2(ah0, hv.x, w1.x); FMA2(ah1, hv.y, w1.y);
        }
        {
            const float cand = tanhf(xhb + pair_sum(ah0) + pair_sum(ah1));
            const float hnew = rzhb + (1.0f - rzb) * cand;
            __stcg(&out[(out_b_row + s) * OC + UU + j], hnew);
        }
        bar_arrive(&g_bar2[TT + s], tid);

        // ---- step closure: everyone's h_new for both dirs visible ----
        bar_wait(&g_bar2[s], tid);
        bar_wait(&g_bar2[TT + s], tid);
    }

    // ---- reset barrier state for the next graph replay ----
    bar_arrive(&g_done, tid);            // last action of every block
    if (blockIdx.x == 0) {
        if (tid == 0) {
            while (*(volatile int*)&g_done < NBLK) { }
        }
        __syncthreads();
        for (int i = tid; i < 2 * TT; i += 256) {
            g_bar1[i] = 0;
            g_bar2[i] = 0;
        }
        if (tid == 0) g_done = 0;
    }
}

// ---------------------------------------------------------------------------
extern "C" void kernel_launch(void* const* d_in, const int* in_sizes, int n_in,
                              void* d_out, int out_size)
{
    (void)in_sizes; (void)n_in; (void)out_size;
    const float* x  = (const float*)d_in[0];
    const float* Wf = (const float*)d_in[1];
    const float* Uf = (const float*)d_in[2];
    const float* bf = (const float*)d_in[3];
    const float* Wb = (const float*)d_in[4];
    const float* Ub = (const float*)d_in[5];
    const float* bb = (const float*)d_in[6];
    float* out = (float*)d_out;

    cudaFuncSetAttribute(scan_kernel,
                         cudaFuncAttributeMaxDynamicSharedMemorySize,
                         SCAN_SMEM_BYTES);

    dim3 g1(NG / 128, (BB * TT) / 128, 2);   // 12 x 128 x 2
    xgemm_kernel<<<g1, 256>>>(x, Wf, bf, Wb, bb);

    scan_kernel<<<NBLK, 256, SCAN_SMEM_BYTES>>>(Uf, Ub, out);
}

// round 10
// speedup vs baseline: 1.7889x; 1.7889x over previous
#include <cuda_runtime.h>

#define BB 32
#define TT 512
#define UU 512
#define NG 1536          // 3*U
#define OC 1024          // 2*U output channels

// x-gates scratch: [dir][B*T][3U] fp32 (192 MB, static device allocation)
__device__ float    g_xg[(size_t)2 * BB * TT * NG];
// per-step rh = r * h_prev exchange buffer
__device__ float    g_rh[2 * BB * UU];
// tree barrier state: counters padded to 256B-distinct addresses
__device__ int      g_leaf[16 * 64];     // [dir*8 + leaf] * 64
__device__ int      g_root[2 * 64];      // [dir] * 64
__device__ unsigned g_gen [2 * 64];      // [dir] * 64

__device__ __forceinline__ float hsig(float v) {
    return fminf(fmaxf(0.2f * v + 0.5f, 0.0f), 1.0f);
}

// ---------------------------------------------------------------------------
// Phase 1: Xg[dir][m][n] = x[m][:] @ W_dir[:][n] + bias_dir[n]
// M=16384, K=512, N=1536. BM=BN=128, BK=16, 256 thr, 8x8 reg tile,
// register-prefetch double buffering. (verified in r7/r8)
// ---------------------------------------------------------------------------
#define XS 132           // padded smem row stride (floats)

__global__ void __launch_bounds__(256, 2)
xgemm_kernel(const float* __restrict__ A,
             const float* __restrict__ Wf, const float* __restrict__ bf,
             const float* __restrict__ Wb, const float* __restrict__ bb)
{
    const int dir = blockIdx.z;
    const float* __restrict__ W    = dir ? Wb : Wf;
    const float* __restrict__ bias = dir ? bb : bf;
    const int m0 = blockIdx.y * 128;
    const int n0 = blockIdx.x * 128;

    __shared__ float As[16 * XS];   // [k][m]
    __shared__ float Bs[16 * XS];   // [k][n]

    const int tid = threadIdx.x;
    const int tx = tid & 15;        // n group (8 cols)
    const int ty = tid >> 4;        // m group (8 rows)

    const int arow = tid >> 1;             // 0..127
    const int akq  = (tid & 1) << 3;       // 0 or 8
    const int bk = tid >> 4;               // 0..15
    const int bn = (tid & 15) << 3;        // 0..120

    const float* Aptr = A + (size_t)(m0 + arow) * 512 + akq;
    const float* Wptr = W + (size_t)bk * NG + n0 + bn;

    float acc[8][8];
#pragma unroll
    for (int i = 0; i < 8; ++i)
#pragma unroll
        for (int j = 0; j < 8; ++j) acc[i][j] = 0.0f;

    float4 a0 = *(const float4*)(Aptr + 0);
    float4 a1 = *(const float4*)(Aptr + 4);
    float4 b0 = *(const float4*)(Wptr + 0);
    float4 b1 = *(const float4*)(Wptr + 4);

    {
        float av[8] = {a0.x,a0.y,a0.z,a0.w,a1.x,a1.y,a1.z,a1.w};
#pragma unroll
        for (int j = 0; j < 8; ++j) As[(akq + j) * XS + arow] = av[j];
        *(float4*)&Bs[bk * XS + bn]     = b0;
        *(float4*)&Bs[bk * XS + bn + 4] = b1;
    }
    __syncthreads();

    for (int kt = 0; kt < 32; ++kt) {
        const int k_next = (kt + 1) << 4;
        if (kt < 31) {
            a0 = *(const float4*)(Aptr + k_next + 0);
            a1 = *(const float4*)(Aptr + k_next + 4);
            b0 = *(const float4*)(Wptr + (size_t)k_next * NG + 0);
            b1 = *(const float4*)(Wptr + (size_t)k_next * NG + 4);
        }

#pragma unroll
        for (int kk = 0; kk < 16; ++kk) {
            float4 av0 = *(const float4*)&As[kk * XS + ty * 8];
            float4 av1 = *(const float4*)&As[kk * XS + ty * 8 + 4];
            float4 bv0 = *(const float4*)&Bs[kk * XS + tx * 8];
            float4 bv1 = *(const float4*)&Bs[kk * XS + tx * 8 + 4];
            float aa[8]  = {av0.x,av0.y,av0.z,av0.w,av1.x,av1.y,av1.z,av1.w};
            float bb2[8] = {bv0.x,bv0.y,bv0.z,bv0.w,bv1.x,bv1.y,bv1.z,bv1.w};
#pragma unroll
            for (int i = 0; i < 8; ++i)
#pragma unroll
                for (int j = 0; j < 8; ++j)
                    acc[i][j] = fmaf(aa[i], bb2[j], acc[i][j]);
        }

        if (kt < 31) {
            __syncthreads();
            float av[8] = {a0.x,a0.y,a0.z,a0.w,a1.x,a1.y,a1.z,a1.w};
#pragma unroll
            for (int j = 0; j < 8; ++j) As[(akq + j) * XS + arow] = av[j];
            *(float4*)&Bs[bk * XS + bn]     = b0;
            *(float4*)&Bs[bk * XS + bn + 4] = b1;
            __syncthreads();
        }
    }

    float* __restrict__ Cd = g_xg + (size_t)dir * BB * TT * NG;
    const int nbase = n0 + tx * 8;
    float4 bi0 = *(const float4*)(bias + nbase);
    float4 bi1 = *(const float4*)(bias + nbase + 4);
#pragma unroll
    for (int i = 0; i < 8; ++i) {
        const int m = m0 + ty * 8 + i;
        float4 o0, o1;
        o0.x = acc[i][0] + bi0.x; o0.y = acc[i][1] + bi0.y;
        o0.z = acc[i][2] + bi0.z; o0.w = acc[i][3] + bi0.w;
        o1.x = acc[i][4] + bi1.x; o1.y = acc[i][5] + bi1.y;
        o1.z = acc[i][6] + bi1.z; o1.w = acc[i][7] + bi1.w;
        *(float4*)&Cd[(size_t)m * NG + nbase]     = o0;
        *(float4*)&Cd[(size_t)m * NG + nbase + 4] = o1;
    }
}

// ---------------------------------------------------------------------------
// Two-level tree grid barrier per direction (64 blocks = 8 leaves x 8).
// Leaf/root counters padded to distinct 256B addresses => atomic
// serialization ~800 cyc instead of ~3200 (single-counter, 64 arrivals).
// Generation-based release survives graph replays (bar_t seeded from g_gen).
// ---------------------------------------------------------------------------
__device__ __forceinline__ void grid_bar(int dir, int leaf, int tid,
                                         unsigned& bar_t)
{
    __threadfence();                       // release global writes
    __syncthreads();                       // all threads' writes fenced
    if (tid == 0) {
        ++bar_t;                           // target generation
        bool released = false;
        if (atomicAdd(&g_leaf[((dir << 3) + leaf) << 6], 1) == 7) {
            atomicExch(&g_leaf[((dir << 3) + leaf) << 6], 0);
            if (atomicAdd(&g_root[dir << 6], 1) == 7) {
                atomicExch(&g_root[dir << 6], 0);
                __threadfence();
                atomicExch(&g_gen[dir << 6], bar_t);
                released = true;
            }
        }
        if (!released) {
            while ((int)(*(volatile unsigned*)&g_gen[dir << 6] - bar_t) < 0) { }
            __threadfence();               // acquire
        }
    }
    __syncthreads();
}

// ---------------------------------------------------------------------------
// Phase 2: persistent scan (r5 structure — best measured). 128 blocks x 256.
// Block = (dir, 8 cols). Per step: zr gates -> g_rh -> bar -> cand -> out -> bar.
// smem: sW 3*512*8 = 12288 | sH 32*513 = 16416 | red 2048  = 30752 floats
// ---------------------------------------------------------------------------
#define SCAN_SMEM_FLOATS (12288 + 16416 + 2048)
#define SCAN_SMEM_BYTES  (SCAN_SMEM_FLOATS * 4)

__global__ void __launch_bounds__(256, 1)
scan_kernel(const float* __restrict__ Uf,
            const float* __restrict__ Ub,
            float* __restrict__ out)
{
    extern __shared__ float sm[];
    float* sW  = sm;             // [g][u][c] : g*4096 + u*8 + c
    float* sH  = sm + 12288;     // [b][u]    : b*513 + u   (h_prev, then rh)
    float* red = sH + 16416;     // reduction scratch

    const int tid   = threadIdx.x;
    const int dir   = blockIdx.x >> 6;
    const int cg    = blockIdx.x & 63;
    const int leaf  = cg >> 3;
    const int hbase = cg << 3;
    const float* __restrict__ Urec = dir ? Ub : Uf;

    // --- weight slice, loaded ONCE: sW[g][u][c] = Urec[u][g*512 + hbase + c]
#pragma unroll 4
    for (int i = tid; i < 12288; i += 256) {
        const int c = i & 7;
        const int u = (i >> 3) & 511;
        const int g = i >> 12;
        sW[i] = Urec[(size_t)u * NG + g * UU + hbase + c];
    }

    unsigned bar_t = 0;
    if (tid == 0) bar_t = *(volatile unsigned*)&g_gen[dir << 6];

    // GEMM-thread mapping
    const int ks = tid >> 6;            // 0..3 (K quarter)
    const int bg = (tid >> 3) & 7;      // 0..7 (batch group of 4)
    const int c  = tid & 7;             // 0..7 (column)
    const int u0 = ks << 7;
    // reduce-thread mapping
    const int rb = tid >> 3;            // 0..31 (batch)
    const int rc = tid & 7;             // 0..7  (column)
    const int j  = hbase + rc;

    const float* __restrict__ pw = sW + (u0 << 3) + c;
    const float* __restrict__ h0 = sH + (bg * 4 + 0) * 513 + u0;
    const float* __restrict__ h1 = h0 + 513;
    const float* __restrict__ h2 = h1 + 513;
    const float* __restrict__ h3 = h2 + 513;

    const size_t xg_base = (size_t)dir * BB * TT + (size_t)rb * TT;
    const int    rh_base = (dir * BB) << 9;

    float rz = 0.0f, rzh = 0.0f;        // z and z*h carried A -> B per thread

    for (int s = 0; s < TT; ++s) {
        // prefetch x-gate values (hidden under the FMA loops)
        const int t_x = dir ? (TT - 1 - s) : s;
        const float* __restrict__ xrow = g_xg + (xg_base + t_x) * NG;
        const float xz = xrow[j];
        const float xr = xrow[UU + j];
        const float xh = xrow[2 * UU + j];

        // ---- load h_prev into sH (L2 only: other blocks wrote it) ----
        if (s == 0) {
            for (int i = tid; i < 16416; i += 256) sH[i] = 0.0f;
        } else {
            const float* __restrict__ hp_base =
                out + (size_t)(s - 1) * OC + (size_t)dir * UU;
#pragma unroll 4
            for (int i = tid; i < 4096; i += 256) {
                const int b  = i >> 7;
                const int u4 = (i & 127) << 2;
                float4 v = __ldcg((const float4*)(hp_base + (size_t)b * TT * OC + u4));
                float* d = sH + b * 513 + u4;
                d[0] = v.x; d[1] = v.y; d[2] = v.z; d[3] = v.w;
            }
        }
        __syncthreads();

        // ---- phase A: z/r gate GEMM ----
        float az0 = 0.f, az1 = 0.f, az2 = 0.f, az3 = 0.f;
        float ar0 = 0.f, ar1 = 0.f, ar2 = 0.f, ar3 = 0.f;
#pragma unroll 8
        for (int uu = 0; uu < 128; ++uu) {
            const float wz = pw[uu * 8];
            const float wr = pw[uu * 8 + 4096];
            const float v0 = h0[uu];
            const float v1 = h1[uu];
            const float v2 = h2[uu];
            const float v3 = h3[uu];
            az0 = fmaf(v0, wz, az0); ar0 = fmaf(v0, wr, ar0);
            az1 = fmaf(v1, wz, az1); ar1 = fmaf(v1, wr, ar1);
            az2 = fmaf(v2, wz, az2); ar2 = fmaf(v2, wr, ar2);
            az3 = fmaf(v3, wz, az3); ar3 = fmaf(v3, wr, ar3);
        }
        {
            float* rp = red + ks * 512 + (bg * 4) * 16 + c;
            rp[0]  = az0; rp[8]  = ar0;
            rp[16] = az1; rp[24] = ar1;
            rp[32] = az2; rp[40] = ar2;
            rp[48] = az3; rp[56] = ar3;
        }
        __syncthreads();
        {
            const float* rr = red + rb * 16 + rc;
            const float hz = rr[0] + rr[512] + rr[1024] + rr[1536];
            const float hr = rr[8] + rr[520] + rr[1032] + rr[1544];
            const float z  = hsig(xz + hz);
            const float r  = hsig(xr + hr);
            const float hp = sH[rb * 513 + j];
            rz  = z;
            rzh = z * hp;
            g_rh[rh_base + (rb << 9) + j] = r * hp;
        }
        grid_bar(dir, leaf, tid, bar_t);

        // ---- load rh into sH (overwrite; L2 only) ----
#pragma unroll 4
        for (int i = tid; i < 4096; i += 256) {
            const int b  = i >> 7;
            const int u4 = (i & 127) << 2;
            float4 v = __ldcg((const float4*)(g_rh + rh_base + (b << 9) + u4));
            float* d = sH + b * 513 + u4;
            d[0] = v.x; d[1] = v.y; d[2] = v.z; d[3] = v.w;
        }
        __syncthreads();

        // ---- phase B: candidate GEMM (Uh at sW offset 8192) ----
        float ah0 = 0.f, ah1 = 0.f, ah2 = 0.f, ah3 = 0.f;
#pragma unroll 8
        for (int uu = 0; uu < 128; ++uu) {
            const float wh = pw[uu * 8 + 8192];
            ah0 = fmaf(h0[uu], wh, ah0);
            ah1 = fmaf(h1[uu], wh, ah1);
            ah2 = fmaf(h2[uu], wh, ah2);
            ah3 = fmaf(h3[uu], wh, ah3);
        }
        {
            float* rp = red + ks * 256 + (bg * 4) * 8 + c;
            rp[0]  = ah0;
            rp[8]  = ah1;
            rp[16] = ah2;
            rp[24] = ah3;
        }
        __syncthreads();
        {
            const float* rr = red + rb * 8 + rc;
            const float hh   = rr[0] + rr[256] + rr[512] + rr[768];
            const float cand = tanhf(xh + hh);
            const float hnew = rzh + (1.0f - rz) * cand;
            out[((size_t)rb * TT + s) * OC + (size_t)dir * UU + j] = hnew;
        }
        grid_bar(dir, leaf, tid, bar_t);
    }
}

// ---------------------------------------------------------------------------
extern "C" void kernel_launch(void* const* d_in, const int* in_sizes, int n_in,
                              void* d_out, int out_size)
{
    (void)in_sizes; (void)n_in; (void)out_size;
    const float* x  = (const float*)d_in[0];
    const float* Wf = (const float*)d_in[1];
    const float* Uf = (const float*)d_in[2];
    const float* bf = (const float*)d_in[3];
    const float* Wb = (const float*)d_in[4];
    const float* Ub = (const float*)d_in[5];
    const float* bb = (const float*)d_in[6];
    float* out = (float*)d_out;

    cudaFuncSetAttribute(scan_kernel,
                         cudaFuncAttributeMaxDynamicSharedMemorySize,
                         SCAN_SMEM_BYTES);

    dim3 g1(NG / 128, (BB * TT) / 128, 2);   // 12 x 128 x 2
    xgemm_kernel<<<g1, 256>>>(x, Wf, bf, Wb, bb);

    scan_kernel<<<128, 256, SCAN_SMEM_BYTES>>>(Uf, Ub, out);
}